// round 9
// baseline (speedup 1.0000x reference)
#include <cuda_runtime.h>
#include <math.h>
#include <float.h>

// Problem constants
#define NS 25      // support count (WAY*SHOT)
#define NQ 75      // query count (WAY*QUERY_SHOT)
#define DD 640     // feature dim
#define MM 25      // M (inner dim)

// Scratch (device globals)
__device__ float g_P[NQ * NS * DD];        // P[q][s][d] = sum_m S[s,d,m]*W[s,q,m]
__device__ float g_part[NQ * NS * 8];      // per-(q,s): 5 chunk partials (pad 8)

// ---------------------------------------------------------------------------
// Kernel 1: per-s GEMM. P[q][s][d] = sum_m W[s,q,m] * S[s,d,m]
// grid = (10 d-chunks of 64, 25 s) = 250 blocks, block = 480 (15 warps).
// Each warp: 5 q rows x 64 d (float2 per lane). 3750 warps total (~25/SM,
// 2 blocks/SM) vs 1875 before -> latency hiding for the LDS->FFMA chains.
// ---------------------------------------------------------------------------
__global__ __launch_bounds__(480) void k1_proj_support(
        const float* __restrict__ fm, const float* __restrict__ w2) {
    const int s  = blockIdx.y;
    const int d0 = blockIdx.x * 64;

    __shared__ __align__(16) float Wsm[MM][76];  // [m][q], 75 q (+pad)
    __shared__ __align__(16) float Ssm[MM][68];  // [m][d], 64 d (+pad)

    const int tid = threadIdx.x;  // 480

    for (int idx = tid; idx < NQ * MM; idx += 480) {
        int q = idx / MM, m = idx - (idx / MM) * MM;
        Wsm[m][q] = w2[s * (NQ * MM) + idx];
    }
    for (int idx = tid; idx < 64 * MM; idx += 480) {
        int d = idx / MM, m = idx - (idx / MM) * MM;
        Ssm[m][d] = fm[s * (DD * MM) + d0 * MM + idx];
    }
    __syncthreads();

    const int lane = tid & 31;
    const int qb   = (tid >> 5) * 5;   // warp -> q base (0..70)

    float acc[5][2];
#pragma unroll
    for (int j = 0; j < 5; j++) { acc[j][0] = 0.0f; acc[j][1] = 0.0f; }

#pragma unroll
    for (int m = 0; m < MM; m++) {
        float2 bv = *reinterpret_cast<const float2*>(&Ssm[m][lane * 2]);
#pragma unroll
        for (int j = 0; j < 5; j++) {
            float a = Wsm[m][qb + j];
            acc[j][0] = fmaf(a, bv.x, acc[j][0]);
            acc[j][1] = fmaf(a, bv.y, acc[j][1]);
        }
    }

#pragma unroll
    for (int j = 0; j < 5; j++) {
        int q = qb + j;
        float2 v = make_float2(acc[j][0], acc[j][1]);
        *reinterpret_cast<float2*>(&g_P[(q * NS + s) * DD + d0 + lane * 2]) = v;
    }
}

// ---------------------------------------------------------------------------
// Kernel 2: per-(q, d-chunk) GEMM + partial L2 writeout. NO atomics/fences.
// grid = (5 d-chunks of 128, 75 q), block = 448 (14 warps).
// Each warp owns 2 s rows; lanes own 4 d (float4); P prefetched at entry.
// Block ends at a plain STG of its partial — minimal tail.
// ---------------------------------------------------------------------------
__global__ __launch_bounds__(448) void k2_query_partial(
        const float* __restrict__ fm, const float* __restrict__ w2) {
    const int q     = blockIdx.y;
    const int chunk = blockIdx.x;
    const int d0    = chunk * 128;

    __shared__ __align__(16) float Wsm[MM][36];   // [m][s], s padded to 32
    __shared__ __align__(16) float Qsm[MM][132];  // [m][d], 128 d (+pad)

    const int tid  = threadIdx.x;  // 448
    const int lane = tid & 31;
    const int warp = tid >> 5;     // 0..13
    const int sb   = warp * 2;     // s base (0..26), even

    // Prefetch P for the epilogue (independent of the r-GEMM)
    float4 pv0 = make_float4(0.f, 0.f, 0.f, 0.f);
    float4 pv1 = make_float4(0.f, 0.f, 0.f, 0.f);
    if (sb < NS)
        pv0 = *reinterpret_cast<const float4*>(
            &g_P[(q * NS + sb) * DD + d0 + lane * 4]);
    if (sb + 1 < NS)
        pv1 = *reinterpret_cast<const float4*>(
            &g_P[(q * NS + sb + 1) * DD + d0 + lane * 4]);

    // Stage W[:,q,:] and Q[q, chunk, :]
    for (int idx = tid; idx < NS * MM; idx += 448) {
        int sI = idx / MM, m = idx - (idx / MM) * MM;
        Wsm[m][sI] = w2[(sI * NQ + q) * MM + m];
    }
    for (int idx = tid; idx < 7 * MM; idx += 448) {       // zero-pad s=25..31
        int m = idx % MM, sI = NS + idx / MM;
        Wsm[m][sI] = 0.0f;
    }
    for (int idx = tid; idx < 128 * MM; idx += 448) {
        int d = idx / MM, m = idx - (idx / MM) * MM;
        Qsm[m][d] = fm[(NS + q) * (DD * MM) + d0 * MM + idx];
    }
    __syncthreads();

    float acc[2][4];
#pragma unroll
    for (int j = 0; j < 2; j++)
#pragma unroll
        for (int i = 0; i < 4; i++) acc[j][i] = 0.0f;

#pragma unroll
    for (int m = 0; m < MM; m++) {
        float4 bv = *reinterpret_cast<const float4*>(&Qsm[m][lane * 4]);
        float2 av = *reinterpret_cast<const float2*>(&Wsm[m][sb]);  // LDS.64
        acc[0][0] = fmaf(av.x, bv.x, acc[0][0]);
        acc[0][1] = fmaf(av.x, bv.y, acc[0][1]);
        acc[0][2] = fmaf(av.x, bv.z, acc[0][2]);
        acc[0][3] = fmaf(av.x, bv.w, acc[0][3]);
        acc[1][0] = fmaf(av.y, bv.x, acc[1][0]);
        acc[1][1] = fmaf(av.y, bv.y, acc[1][1]);
        acc[1][2] = fmaf(av.y, bv.z, acc[1][2]);
        acc[1][3] = fmaf(av.y, bv.w, acc[1][3]);
    }

    // Epilogue: (r - p)^2, lane reduce, plain STG of the partial. Done.
    {
        float t0 = acc[0][0] - pv0.x;
        float t1 = acc[0][1] - pv0.y;
        float t2 = acc[0][2] - pv0.z;
        float t3 = acc[0][3] - pv0.w;
        float part = t0 * t0 + t1 * t1 + t2 * t2 + t3 * t3;
#pragma unroll
        for (int off = 16; off > 0; off >>= 1)
            part += __shfl_down_sync(0xffffffffu, part, off);
        if (lane == 0 && sb < NS)
            g_part[(q * NS + sb) * 8 + chunk] = part;
    }
    {
        float t0 = acc[1][0] - pv1.x;
        float t1 = acc[1][1] - pv1.y;
        float t2 = acc[1][2] - pv1.z;
        float t3 = acc[1][3] - pv1.w;
        float part = t0 * t0 + t1 * t1 + t2 * t2 + t3 * t3;
#pragma unroll
        for (int off = 16; off > 0; off >>= 1)
            part += __shfl_down_sync(0xffffffffu, part, off);
        if (lane == 0 && sb + 1 < NS)
            g_part[(q * NS + sb + 1) * 8 + chunk] = part;
    }
}

// ---------------------------------------------------------------------------
// Kernel 3: sum 5 partials per (q,s), scale, log-softmax over s.
// grid = 75, block = 32 (one warp per query row).
// ---------------------------------------------------------------------------
__global__ void k3_softmax(const float* __restrict__ scale,
                           float* __restrict__ out) {
    const int q    = blockIdx.x;
    const int lane = threadIdx.x;

    const float c = -scale[0] / 312500.0f;  // 1/(M^2 * G*Q*Q*SHOT)

    float raw = 0.0f;
    if (lane < NS) {
        const float* p = &g_part[(q * NS + lane) * 8];
        float4 v = *reinterpret_cast<const float4*>(p);   // chunks 0..3
        raw = v.x + v.y + v.z + v.w + p[4];               // + chunk 4
    }
    float logit = (lane < NS) ? raw * c : -FLT_MAX;

    float mx = logit;
#pragma unroll
    for (int off = 16; off > 0; off >>= 1)
        mx = fmaxf(mx, __shfl_xor_sync(0xffffffffu, mx, off));

    float e = (lane < NS) ? expf(logit - mx) : 0.0f;
    float sum = e;
#pragma unroll
    for (int off = 16; off > 0; off >>= 1)
        sum += __shfl_xor_sync(0xffffffffu, sum, off);

    if (lane < NS)
        out[q * NS + lane] = logit - mx - logf(sum);
}

// ---------------------------------------------------------------------------
extern "C" void kernel_launch(void* const* d_in, const int* in_sizes, int n_in,
                              void* d_out, int out_size) {
    const float* fm    = (const float*)d_in[0];  // (100, 640, 25) f32
    const float* w2    = (const float*)d_in[1];  // (25, 75, 25) f32
    const float* scale = (const float*)d_in[2];  // (1,) f32
    float* out = (float*)d_out;                  // (75, 25) f32

    k1_proj_support<<<dim3(10, 25), 480>>>(fm, w2);
    k2_query_partial<<<dim3(5, NQ), 448>>>(fm, w2);
    k3_softmax<<<NQ, 32>>>(scale, out);
}

// round 10
// speedup vs baseline: 1.0966x; 1.0966x over previous
#include <cuda_runtime.h>
#include <math.h>
#include <float.h>

// Problem constants
#define NS 25      // support count (WAY*SHOT)
#define NQ 75      // query count (WAY*QUERY_SHOT)
#define DD 640     // feature dim
#define MM 25      // M (inner dim)

// Scratch (device globals)
__device__ float g_P[NQ * NS * DD];        // P[q][s][d] = sum_m S[s,d,m]*W[s,q,m]
__device__ float g_part[NQ * NS * 8];      // per-(q,s): 5 chunk partials (pad 8)

// ---------------------------------------------------------------------------
// Kernel 1: per-s GEMM. P[q][s][d] = sum_m W[s,q,m] * S[s,d,m]
// grid = (5 d-chunks of 128, 25 s) = 125 blocks (SINGLE WAVE on 148 SMs),
// block = 800 (25 warps). Each warp: 3 q rows x 128 d (float4 per lane);
// 25 warps x 3 q = 75 q exactly. 25 warps/SM vs 15 before, no extra wave.
// ---------------------------------------------------------------------------
__global__ __launch_bounds__(800) void k1_proj_support(
        const float* __restrict__ fm, const float* __restrict__ w2) {
    const int s  = blockIdx.y;
    const int d0 = blockIdx.x * 128;

    __shared__ __align__(16) float Wsm[MM][76];   // [m][q], 75 q (+pad)
    __shared__ __align__(16) float Ssm[MM][132];  // [m][d], 128 d (+pad)

    const int tid = threadIdx.x;  // 800

    for (int idx = tid; idx < NQ * MM; idx += 800) {
        int q = idx / MM, m = idx - (idx / MM) * MM;
        Wsm[m][q] = w2[s * (NQ * MM) + idx];
    }
    for (int idx = tid; idx < 128 * MM; idx += 800) {
        int d = idx / MM, m = idx - (idx / MM) * MM;
        Ssm[m][d] = fm[s * (DD * MM) + d0 * MM + idx];
    }
    __syncthreads();

    const int lane = tid & 31;
    const int qb   = (tid >> 5) * 3;   // warp -> q base (0..72)

    float acc[3][4];
#pragma unroll
    for (int j = 0; j < 3; j++)
#pragma unroll
        for (int i = 0; i < 4; i++) acc[j][i] = 0.0f;

#pragma unroll
    for (int m = 0; m < MM; m++) {
        float4 bv = *reinterpret_cast<const float4*>(&Ssm[m][lane * 4]);
#pragma unroll
        for (int j = 0; j < 3; j++) {
            float a = Wsm[m][qb + j];
            acc[j][0] = fmaf(a, bv.x, acc[j][0]);
            acc[j][1] = fmaf(a, bv.y, acc[j][1]);
            acc[j][2] = fmaf(a, bv.z, acc[j][2]);
            acc[j][3] = fmaf(a, bv.w, acc[j][3]);
        }
    }

#pragma unroll
    for (int j = 0; j < 3; j++) {
        int q = qb + j;
        float4 v = make_float4(acc[j][0], acc[j][1], acc[j][2], acc[j][3]);
        *reinterpret_cast<float4*>(&g_P[(q * NS + s) * DD + d0 + lane * 4]) = v;
    }
}

// ---------------------------------------------------------------------------
// Kernel 2: per-(q, d-chunk) GEMM + partial L2 writeout. NO atomics/fences.
// grid = (5 d-chunks of 128, 75 q), block = 448 (14 warps).
// Each warp owns 2 s rows; lanes own 4 d (float4); P prefetched at entry.
// Block ends at a plain STG of its partial — minimal tail.
// ---------------------------------------------------------------------------
__global__ __launch_bounds__(448) void k2_query_partial(
        const float* __restrict__ fm, const float* __restrict__ w2) {
    const int q     = blockIdx.y;
    const int chunk = blockIdx.x;
    const int d0    = chunk * 128;

    __shared__ __align__(16) float Wsm[MM][36];   // [m][s], s padded to 32
    __shared__ __align__(16) float Qsm[MM][132];  // [m][d], 128 d (+pad)

    const int tid  = threadIdx.x;  // 448
    const int lane = tid & 31;
    const int warp = tid >> 5;     // 0..13
    const int sb   = warp * 2;     // s base (0..26), even

    // Prefetch P for the epilogue (independent of the r-GEMM)
    float4 pv0 = make_float4(0.f, 0.f, 0.f, 0.f);
    float4 pv1 = make_float4(0.f, 0.f, 0.f, 0.f);
    if (sb < NS)
        pv0 = *reinterpret_cast<const float4*>(
            &g_P[(q * NS + sb) * DD + d0 + lane * 4]);
    if (sb + 1 < NS)
        pv1 = *reinterpret_cast<const float4*>(
            &g_P[(q * NS + sb + 1) * DD + d0 + lane * 4]);

    // Stage W[:,q,:] and Q[q, chunk, :]
    for (int idx = tid; idx < NS * MM; idx += 448) {
        int sI = idx / MM, m = idx - (idx / MM) * MM;
        Wsm[m][sI] = w2[(sI * NQ + q) * MM + m];
    }
    for (int idx = tid; idx < 7 * MM; idx += 448) {       // zero-pad s=25..31
        int m = idx % MM, sI = NS + idx / MM;
        Wsm[m][sI] = 0.0f;
    }
    for (int idx = tid; idx < 128 * MM; idx += 448) {
        int d = idx / MM, m = idx - (idx / MM) * MM;
        Qsm[m][d] = fm[(NS + q) * (DD * MM) + d0 * MM + idx];
    }
    __syncthreads();

    float acc[2][4];
#pragma unroll
    for (int j = 0; j < 2; j++)
#pragma unroll
        for (int i = 0; i < 4; i++) acc[j][i] = 0.0f;

#pragma unroll
    for (int m = 0; m < MM; m++) {
        float4 bv = *reinterpret_cast<const float4*>(&Qsm[m][lane * 4]);
        float2 av = *reinterpret_cast<const float2*>(&Wsm[m][sb]);  // LDS.64
        acc[0][0] = fmaf(av.x, bv.x, acc[0][0]);
        acc[0][1] = fmaf(av.x, bv.y, acc[0][1]);
        acc[0][2] = fmaf(av.x, bv.z, acc[0][2]);
        acc[0][3] = fmaf(av.x, bv.w, acc[0][3]);
        acc[1][0] = fmaf(av.y, bv.x, acc[1][0]);
        acc[1][1] = fmaf(av.y, bv.y, acc[1][1]);
        acc[1][2] = fmaf(av.y, bv.z, acc[1][2]);
        acc[1][3] = fmaf(av.y, bv.w, acc[1][3]);
    }

    // Epilogue: (r - p)^2, lane reduce, plain STG of the partial. Done.
    {
        float t0 = acc[0][0] - pv0.x;
        float t1 = acc[0][1] - pv0.y;
        float t2 = acc[0][2] - pv0.z;
        float t3 = acc[0][3] - pv0.w;
        float part = t0 * t0 + t1 * t1 + t2 * t2 + t3 * t3;
#pragma unroll
        for (int off = 16; off > 0; off >>= 1)
            part += __shfl_down_sync(0xffffffffu, part, off);
        if (lane == 0 && sb < NS)
            g_part[(q * NS + sb) * 8 + chunk] = part;
    }
    {
        float t0 = acc[1][0] - pv1.x;
        float t1 = acc[1][1] - pv1.y;
        float t2 = acc[1][2] - pv1.z;
        float t3 = acc[1][3] - pv1.w;
        float part = t0 * t0 + t1 * t1 + t2 * t2 + t3 * t3;
#pragma unroll
        for (int off = 16; off > 0; off >>= 1)
            part += __shfl_down_sync(0xffffffffu, part, off);
        if (lane == 0 && sb + 1 < NS)
            g_part[(q * NS + sb + 1) * 8 + chunk] = part;
    }
}

// ---------------------------------------------------------------------------
// Kernel 3: sum 5 partials per (q,s), scale, log-softmax over s.
// grid = 75, block = 32 (one warp per query row).
// ---------------------------------------------------------------------------
__global__ void k3_softmax(const float* __restrict__ scale,
                           float* __restrict__ out) {
    const int q    = blockIdx.x;
    const int lane = threadIdx.x;

    const float c = -scale[0] / 312500.0f;  // 1/(M^2 * G*Q*Q*SHOT)

    float raw = 0.0f;
    if (lane < NS) {
        const float* p = &g_part[(q * NS + lane) * 8];
        float4 v = *reinterpret_cast<const float4*>(p);   // chunks 0..3
        raw = v.x + v.y + v.z + v.w + p[4];               // + chunk 4
    }
    float logit = (lane < NS) ? raw * c : -FLT_MAX;

    float mx = logit;
#pragma unroll
    for (int off = 16; off > 0; off >>= 1)
        mx = fmaxf(mx, __shfl_xor_sync(0xffffffffu, mx, off));

    float e = (lane < NS) ? expf(logit - mx) : 0.0f;
    float sum = e;
#pragma unroll
    for (int off = 16; off > 0; off >>= 1)
        sum += __shfl_xor_sync(0xffffffffu, sum, off);

    if (lane < NS)
        out[q * NS + lane] = logit - mx - logf(sum);
}

// ---------------------------------------------------------------------------
extern "C" void kernel_launch(void* const* d_in, const int* in_sizes, int n_in,
                              void* d_out, int out_size) {
    const float* fm    = (const float*)d_in[0];  // (100, 640, 25) f32
    const float* w2    = (const float*)d_in[1];  // (25, 75, 25) f32
    const float* scale = (const float*)d_in[2];  // (1,) f32
    float* out = (float*)d_out;                  // (75, 25) f32

    k1_proj_support<<<dim3(5, 25), 800>>>(fm, w2);
    k2_query_partial<<<dim3(5, NQ), 448>>>(fm, w2);
    k3_softmax<<<NQ, 32>>>(scale, out);
}